// round 16
// baseline (speedup 1.0000x reference)
#include <cuda_runtime.h>
#include <cuda_bf16.h>
#include <cuda_fp16.h>
#include <cstdint>

#define BB 4
#define CC 64
#define HIN 96
#define WIN 96
#define HOUT 192
#define WOUT 192
#define NPX (HIN*WIN)          // 9216

// Scratch + precomputed data (allocation-free rule: device globals)
__device__ float g_A[BB*NPX*CC];         // fusL@sta, channel-last [b][px][64]
__device__ float g_B[BB*NPX*CC];         // fusR@x,   channel-last
__device__ float g_U[BB*4*NPX*8];        // wc_ci @ x, [b][ci][src][8]
__device__ float g_off[4][2];
__device__ float g_stoff[4][2];
__device__ float g_wcpx[4][512];         // [j*64+c]
__device__ float g_M[4][512];            // [j*64+o]  (fusR @ we_par)
// kc_w repacked: [t 25][q 8][ks 4][lane 32] uint2 = (b0h, b1h) fp16x2 (hi only)
__device__ uint2 g_b[25600];

// ============================ helpers ======================================
__device__ __forceinline__ uint32_t smem_u32(const void* p) {
  uint32_t a;
  asm("{ .reg .u64 t; cvta.to.shared.u64 t, %1; cvt.u32.u64 %0, t; }" : "=r"(a) : "l"(p));
  return a;
}
__device__ __forceinline__ void cp16(uint32_t dst, const float* src) {
  asm volatile("cp.async.cg.shared.global [%0], [%1], 16;" :: "r"(dst), "l"(src));
}
#define CP_COMMIT() asm volatile("cp.async.commit_group;" ::: "memory")
#define CP_WAIT0()  asm volatile("cp.async.wait_group 0;" ::: "memory")

__device__ __forceinline__ uint32_t fp16_pack2(float v0, float v1) {
  __half2 h = __floats2half2_rn(v0, v1);
  return *(uint32_t*)&h;
}

#define MMA_FP16(d, a, b0v, b1v) \
  asm volatile("mma.sync.aligned.m16n8k16.row.col.f32.f16.f16.f32 " \
      "{%0,%1,%2,%3}, {%4,%5,%6,%7}, {%8,%9}, {%0,%1,%2,%3};" \
      : "+f"((d)[0]), "+f"((d)[1]), "+f"((d)[2]), "+f"((d)[3]) \
      : "r"((a)[0]), "r"((a)[1]), "r"((a)[2]), "r"((a)[3]), "r"(b0v), "r"(b1v))

__device__ __forceinline__ float4 f4maf(float s, float4 a, float4 r) {
  r.x = fmaf(s, a.x, r.x); r.y = fmaf(s, a.y, r.y);
  r.z = fmaf(s, a.z, r.z); r.w = fmaf(s, a.w, r.w);
  return r;
}

// ---------------------------------------------------------------------------
// K01: blocks 0..99 repack kc_w -> fp16 hi fragments; blocks 100..103 parity
// ---------------------------------------------------------------------------
__global__ void k01_prep(const float* __restrict__ kcw,
                         const float* __restrict__ b1w, const float* __restrict__ b1b,
                         const float* __restrict__ b2w, const float* __restrict__ b2b,
                         const float* __restrict__ rw,  const float* __restrict__ rb,
                         const float* __restrict__ ow,  const float* __restrict__ ob,
                         const float* __restrict__ sow, const float* __restrict__ sob,
                         const float* __restrict__ wc,  const float* __restrict__ we,
                         const float* __restrict__ fusw) {
  const int tid = threadIdx.x;
  if (blockIdx.x < 100) {
    int idx = blockIdx.x*256 + tid;
    int l  = idx & 31;
    int ks = (idx >> 5) & 3;
    int q  = (idx >> 7) & 7;
    int t  = idx >> 10;
    int g = l >> 2, tg = l & 3;
    int c  = q*8 + g;
    int k0 = ks*16 + 2*tg;
    const float* row = kcw + (c*25 + t)*64;
    g_b[idx] = make_uint2(fp16_pack2(row[k0],     row[k0 + 1]),
                          fp16_pack2(row[k0 + 8], row[k0 + 9]));
    return;
  }
  __shared__ float hid[64], emb[64], r[4];
  __shared__ float s_we2[512];
  __shared__ float s_fr[64*65];
  const int ci = blockIdx.x - 100;
  const float in2 = (ci >> 1) ? 0.25f : -0.25f;
  const float in3 = (ci & 1)  ? 0.25f : -0.25f;

  for (int e = tid; e < 4096; e += 256) {
    int o = e >> 6, c = e & 63;
    s_fr[c*65 + o] = fusw[o*128 + 64 + c];
  }
  if (tid < 64) {
    float a = b1b[tid] + 0.5f*b1w[tid*4+0] + 0.5f*b1w[tid*4+1]
            + in2*b1w[tid*4+2] + in3*b1w[tid*4+3];
    hid[tid] = fmaxf(a, 0.f);
  }
  __syncthreads();
  if (tid < 64) {
    float a = b2b[tid];
    #pragma unroll 8
    for (int k = 0; k < 64; k++) a = fmaf(b2w[tid*64+k], hid[k], a);
    emb[tid] = fmaxf(a, 0.f);
  }
  __syncthreads();
  if (tid < 4) {
    float a = rb[tid];
    for (int k = 0; k < 64; k++) a = fmaf(rw[tid*64+k], emb[k], a);
    r[tid] = 1.f / (1.f + expf(-a));
  } else if (tid < 6) {
    int t = tid - 4; float a = ob[t];
    for (int k = 0; k < 64; k++) a = fmaf(ow[t*64+k], emb[k], a);
    g_off[ci][t] = a;
  } else if (tid < 8) {
    int t = tid - 6; float a = sob[t];
    for (int k = 0; k < 64; k++) a = fmaf(sow[t*64+k], emb[k], a);
    g_stoff[ci][t] = a;
  }
  __syncthreads();
  for (int e = tid; e < 512; e += 256) {
    float a = 0.f, bsum = 0.f;
    #pragma unroll
    for (int ex = 0; ex < 4; ex++) {
      a    = fmaf(r[ex], wc[ex*512+e], a);
      bsum = fmaf(r[ex], we[ex*512+e], bsum);
    }
    g_wcpx[ci][e] = a;
    s_we2[e] = bsum;
  }
  __syncthreads();
  for (int e = tid; e < 512; e += 256) {
    int j = e >> 6, o = e & 63;
    float a = 0.f;
    #pragma unroll 8
    for (int c = 0; c < 64; c++) a = fmaf(s_fr[c*65 + o], s_we2[c*8 + j], a);
    g_M[ci][j*64 + o] = a;
  }
}

// ---------------------------------------------------------------------------
// K2 v11: fp16 single-term mma loop (R13-proven) + FUSED epilogue computing
// A = fusL@sta, B = fusR@x, U = wc_ci@x  (kprep1 deleted).
// Block: 256 thr / 8 warps, tile (b, 2 rows, 32 px), M=64. 3 blocks/SM.
// smem floats: 12608 (loop: s_b 4096 | s_x 6912 | s_kb 1600;
//              epi: s_sta/s_xt 4224 @0 | s_fl/s_fr 4352 @4224 | swc 2048 @8576)
// ---------------------------------------------------------------------------
#define K2_SMEM_FLOATS (4096 + 6912 + 1600)

__global__ __launch_bounds__(256, 3) void k2_sta_mma(const float* __restrict__ x,
                                                     const float* __restrict__ st,
                                                     const float* __restrict__ kcb,
                                                     const float* __restrict__ fusw) {
  extern __shared__ float sm[];
  float* s_b  = sm;                // [2][512 uint4] = 2x8KB
  float* s_x  = sm + 4096;         // [c 64][slot 3][36]
  float* s_kb = sm + 11008;        // [1600]
  // post-loop reuse:
  float* s_sta = sm;               // phase A: [c 64][px 66]; phase B: x tile
  float* s_fl  = sm + 4224;        // phase A: fusL^T [k][68]; phase B: fusR^T
  float* s_wc  = sm + 8576;        // [4][512]

  const int b = blockIdx.z, h0 = blockIdx.y*2, w0 = blockIdx.x*32;
  const int tid = threadIdx.x, wid = tid >> 5, l = tid & 31;
  const int g = l >> 2, tg = l & 3;
  const int mt = wid & 3, nth = wid >> 2;
  const uint32_t sb = smem_u32(s_b);

  // B(0) prologue: 8KB = 512 x 16B chunks
  {
    const float* src = (const float*)g_b;
    #pragma unroll
    for (int i = 0; i < 2; i++) {
      int j = tid + i*256;
      cp16(sb + (uint32_t)j*16u, src + j*4);
    }
    CP_COMMIT();
  }

  // x rows 0..2 into slots 0..2
  for (int e = tid; e < 64*3*36; e += 256) {
    int col = e % 36; int slot = (e / 36) % 3; int c = e / 108;
    int gy = min(max(h0 - 2 + slot, 0), HIN - 1);
    int gx = min(max(w0 - 2 + col, 0), WIN - 1);
    s_x[c*108 + slot*36 + col] = x[((b*CC + c)*HIN + gy)*WIN + gx];
  }
  for (int e = tid; e < 1600; e += 256) s_kb[e] = kcb[e];

  // A fragments (fp16 hi) direct from gmem, tap-invariant
  uint32_t ahi[4][4];
  {
    const int pxg = mt*16 + g, pxg8 = pxg + 8;
    const int r0 = h0 + (pxg >> 5),  ca = w0 + (pxg & 31);
    const int r1 = h0 + (pxg8 >> 5), cb2 = w0 + (pxg8 & 31);
    const float* stb = st + (size_t)b*CC*NPX;
    #pragma unroll
    for (int ks = 0; ks < 4; ks++) {
      int kb = ks*16 + 2*tg;
      const float* p0 = stb + (size_t)kb*NPX;
      ahi[ks][0] = fp16_pack2(p0[r0*WIN + ca],         p0[NPX + r0*WIN + ca]);
      ahi[ks][1] = fp16_pack2(p0[r1*WIN + cb2],        p0[NPX + r1*WIN + cb2]);
      ahi[ks][2] = fp16_pack2(p0[8*NPX + r0*WIN + ca], p0[9*NPX + r0*WIN + ca]);
      ahi[ks][3] = fp16_pack2(p0[8*NPX + r1*WIN + cb2], p0[9*NPX + r1*WIN + cb2]);
    }
  }
  __syncthreads();

  float sacc[16];
  #pragma unroll
  for (int i = 0; i < 16; i++) sacc[i] = 0.f;

  const int prow  = mt >> 1;
  const int pcol0 = (mt & 1)*16 + g;

  for (int t = 0; t < 25; t++) {
    const int buf = t & 1;
    CP_WAIT0();
    __syncthreads();
    if (t < 24) {
      const float* src = (const float*)(g_b + (t + 1)*1024);
      const uint32_t nb = sb + (uint32_t)(1 - buf)*8192u;
      #pragma unroll
      for (int i = 0; i < 2; i++) {
        int j = tid + i*256;
        cp16(nb + (uint32_t)j*16u, src + j*4);
      }
      CP_COMMIT();
    }
    if (t == 5 || t == 10 || t == 15) {
      const int rl = t/5 + 2;
      const int slot = rl % 3;
      const int gy = min(max(h0 - 2 + rl, 0), HIN - 1);
      for (int e = tid; e < 2304; e += 256) {
        int col = e % 36; int c = e / 36;
        int gx = min(max(w0 - 2 + col, 0), WIN - 1);
        s_x[c*108 + slot*36 + col] = x[((b*CC + c)*HIN + gy)*WIN + gx];
      }
    }

    const int rr = t / 5, dw = t - rr*5;

    float d[4][4];
    #pragma unroll
    for (int n = 0; n < 4; n++) {
      int c0 = ((nth*4 + n)*8 + 2*tg)*25 + t;
      d[n][0] = s_kb[c0];      d[n][1] = s_kb[c0 + 25];
      d[n][2] = d[n][0];       d[n][3] = d[n][1];
    }

    const uint2* bb = (const uint2*)(s_b + buf*2048);
    #pragma unroll
    for (int ks = 0; ks < 4; ks++) {
      #pragma unroll
      for (int n = 0; n < 4; n++) {
        uint2 bv = bb[((nth*4 + n)*4 + ks)*32 + l];
        MMA_FP16(d[n], ahi[ks], bv.x, bv.y);   // ahi * bhi (single term)
      }
    }

    const int sl = (prow + rr) % 3;
    #pragma unroll
    for (int n = 0; n < 4; n++) {
      int cb = (nth*4 + n)*8 + 2*tg;
      #pragma unroll
      for (int j = 0; j < 4; j++) {
        int c  = cb + (j & 1);
        int px = pcol0 + (j >> 1)*8;
        float gv = d[n][j];
        float lv = fmaf(0.45f, fabsf(gv), 0.55f*gv);
        float xv = s_x[c*108 + sl*36 + px + dw];
        sacc[n*4 + j] = fmaf(lv, xv, sacc[n*4 + j]);
      }
    }
  }

  // ============ fused epilogue: A = fusL@sta, B = fusR@x, U = wc@x =========
  const int o0 = (tid & 15)*4, p0 = (tid >> 4)*4;

  __syncthreads();   // all loop reads of s_b/s_x retired
  // phase A staging: spill sta tile + fusL^T + swc
  #pragma unroll
  for (int n = 0; n < 4; n++) {
    int cb = (nth*4 + n)*8 + 2*tg;
    #pragma unroll
    for (int j = 0; j < 4; j++) {
      int c  = cb + (j & 1);
      int px = prow*32 + pcol0 + (j >> 1)*8;
      s_sta[c*66 + px] = sacc[n*4 + j];
    }
  }
  for (int e = tid; e < 4096; e += 256) {
    int o = e >> 6, k = e & 63;
    s_fl[k*68 + o] = fusw[o*128 + k];
  }
  for (int e = tid; e < 2048; e += 256) s_wc[e] = g_wcpx[e >> 9][e & 511];
  __syncthreads();

  // A GEMM: 64o x 64px, K=64
  {
    float4 acc[4];
    #pragma unroll
    for (int i = 0; i < 4; i++) acc[i] = make_float4(0.f, 0.f, 0.f, 0.f);
    #pragma unroll 4
    for (int c = 0; c < 64; c++) {
      float4 w4 = *(const float4*)&s_fl[c*68 + o0];
      const float* sr = s_sta + c*66 + p0;
      #pragma unroll
      for (int pp = 0; pp < 4; pp++)
        acc[pp] = f4maf(sr[pp], w4, acc[pp]);
    }
    float* dst = g_A + (size_t)b*NPX*CC;
    #pragma unroll
    for (int pp = 0; pp < 4; pp++) {
      int pxt = p0 + pp;
      int gpx = (h0 + (pxt >> 5))*WIN + w0 + (pxt & 31);
      *(float4*)&dst[(size_t)gpx*CC + o0] = acc[pp];
    }
  }
  __syncthreads();   // A GEMM reads done before overwrite

  // phase B staging: x center tile [c][px 0..63] + fusR^T
  for (int e = tid; e < 4096; e += 256) {
    int c = e >> 6, px = e & 63;
    s_sta[c*66 + px] = x[((b*CC + c)*HIN + h0 + (px >> 5))*WIN + w0 + (px & 31)];
  }
  for (int e = tid; e < 4096; e += 256) {
    int o = e >> 6, k = e & 63;
    s_fl[k*68 + o] = fusw[o*128 + 64 + k];
  }
  __syncthreads();

  // B GEMM: 64o x 64px, K=64
  {
    float4 acc[4];
    #pragma unroll
    for (int i = 0; i < 4; i++) acc[i] = make_float4(0.f, 0.f, 0.f, 0.f);
    #pragma unroll 4
    for (int c = 0; c < 64; c++) {
      float4 w4 = *(const float4*)&s_fl[c*68 + o0];
      const float* sr = s_sta + c*66 + p0;
      #pragma unroll
      for (int pp = 0; pp < 4; pp++)
        acc[pp] = f4maf(sr[pp], w4, acc[pp]);
    }
    float* dst = g_B + (size_t)b*NPX*CC;
    #pragma unroll
    for (int pp = 0; pp < 4; pp++) {
      int pxt = p0 + pp;
      int gpx = (h0 + (pxt >> 5))*WIN + w0 + (pxt & 31);
      *(float4*)&dst[(size_t)gpx*CC + o0] = acc[pp];
    }
  }

  // U: thread = (px 64, ci 4): 8 j-dots over c
  {
    const int px = tid & 63, ci = tid >> 6;
    float acc[8];
    #pragma unroll
    for (int j = 0; j < 8; j++) acc[j] = 0.f;
    #pragma unroll 4
    for (int c = 0; c < 64; c++) {
      float xv = s_sta[c*66 + px];
      const float* w = &s_wc[ci*512 + c];
      #pragma unroll
      for (int j = 0; j < 8; j++)
        acc[j] = fmaf(w[j*64], xv, acc[j]);
    }
    int gpx = (h0 + (px >> 5))*WIN + w0 + (px & 31);
    float* dst = g_U + ((size_t)(b*4 + ci)*NPX + gpx)*8;
    *(float4*)dst       = make_float4(acc[0], acc[1], acc[2], acc[3]);
    *(float4*)(dst + 4) = make_float4(acc[4], acc[5], acc[6], acc[7]);
  }
}

// ---------------------------------------------------------------------------
// K3 v4: staged + row-precombined bilinear taps; t via interp of U.
// ---------------------------------------------------------------------------
__global__ __launch_bounds__(256, 4) void k3_fuse(const float* __restrict__ fusb,
                                                  float* __restrict__ out) {
  __shared__ float sAB[4*34*68];
  __shared__ float sU[2*34*8];
  __shared__ float s_M[1024];
  __shared__ float s_fb[64];
  __shared__ float s_w0[2][64], s_w1[2][64];
  __shared__ int   s_lb[2][64];
  __shared__ int   s_rows[2][2][2];
  __shared__ float s_wy[2][2][2];
  __shared__ int   s_fc[2][2];
  __shared__ float s_frc[2][2];
  __shared__ int   s_base[2];

  const int b = blockIdx.z, Y = blockIdx.y, X0 = blockIdx.x * 64;
  const int tid = threadIdx.x;
  const int ph = Y & 1;

  if (tid < 2) {
    const int k = tid;
    int fc0 = 0, fc1 = 0;
    #pragma unroll
    for (int p = 0; p < 2; p++) {
      int ci = ph*2 + p;
      float offx = k ? g_stoff[ci][0] : g_off[ci][0];
      float offy = k ? g_stoff[ci][1] : g_off[ci][1];
      float pyf = (Y + 0.5f)*0.5f - 0.5f + offy;
      float yf = floorf(pyf); int iy = (int)yf; float fy = pyf - yf;
      s_wy[k][p][0] = (iy   >= 0 && iy   <= HIN-1) ? (1.f - fy) : 0.f;
      s_wy[k][p][1] = (iy+1 >= 0 && iy+1 <= HIN-1) ? fy : 0.f;
      s_rows[k][p][0] = min(max(iy, 0), HIN-1);
      s_rows[k][p][1] = min(max(iy+1, 0), HIN-1);
      float xo = (p ? 0.25f : -0.25f) + offx;
      float xf = floorf(xo); int fc = (int)xf;
      s_fc[k][p] = fc; s_frc[k][p] = xo - xf;
      if (p == 0) fc0 = fc; else fc1 = fc;
    }
    s_base[k] = X0/2 + min(fc0, fc1);
  }
  __syncthreads();

  if (tid < 128) {
    int k = tid >> 6, u = tid & 63, p = u & 1;
    int sg = X0/2 + (u >> 1) + s_fc[k][p];
    float fr = s_frc[k][p];
    s_lb[k][u] = sg - s_base[k];
    s_w0[k][u] = (sg   >= 0 && sg   <= WIN-1) ? (1.f - fr) : 0.f;
    s_w1[k][u] = (sg+1 >= 0 && sg+1 <= WIN-1) ? fr : 0.f;
  }

  for (int e = tid; e < 2176; e += 256) {
    int kp = e / 544, rem = e - kp*544;
    int i = rem >> 4, c4 = rem & 15;
    int k = kp >> 1, p = kp & 1;
    int cg = min(max(s_base[k] + i, 0), WIN-1);
    const float4* src = (const float4*)(k ? g_A : g_B) + (size_t)(b*NPX)*16;
    float4 v0 = src[(s_rows[k][p][0]*WIN + cg)*16 + c4];
    float4 v1 = src[(s_rows[k][p][1]*WIN + cg)*16 + c4];
    float wy0 = s_wy[k][p][0], wy1 = s_wy[k][p][1];
    float4 vv;
    vv.x = wy0*v0.x + wy1*v1.x;  vv.y = wy0*v0.y + wy1*v1.y;
    vv.z = wy0*v0.z + wy1*v1.z;  vv.w = wy0*v0.w + wy1*v1.w;
    *(float4*)&sAB[(kp*34 + i)*68 + c4*4] = vv;
  }
  if (tid < 136) {
    int p = tid / 68, rem = tid - p*68;
    int i = rem >> 1, h = rem & 1;
    int ci = ph*2 + p;
    int cg = min(max(s_base[0] + i, 0), WIN-1);
    const float4* src = (const float4*)g_U + ((size_t)(b*4 + ci)*NPX)*2;
    float4 u0 = src[(s_rows[0][p][0]*WIN + cg)*2 + h];
    float4 u1 = src[(s_rows[0][p][1]*WIN + cg)*2 + h];
    float wy0 = s_wy[0][p][0], wy1 = s_wy[0][p][1];
    float4 vv;
    vv.x = wy0*u0.x + wy1*u1.x;  vv.y = wy0*u0.y + wy1*u1.y;
    vv.z = wy0*u0.z + wy1*u1.z;  vv.w = wy0*u0.w + wy1*u1.w;
    *(float4*)&sU[(p*34 + i)*8 + h*4] = vv;
  }
  for (int e = tid; e < 1024; e += 256)
    s_M[e] = g_M[ph*2 + (e >> 9)][e & 511];
  if (tid < 64) s_fb[tid] = fusb[tid];
  __syncthreads();

  const int u = tid & 63, q = tid >> 6, p = u & 1;
  const int   lbB = s_lb[0][u], lbA = s_lb[1][u];
  const float wB0 = s_w0[0][u], wB1 = s_w1[0][u];
  const float wA0 = s_w0[1][u], wA1 = s_w1[1][u];

  float tt[8];
  {
    const float4* Up = (const float4*)&sU[(p*34 + lbB)*8];
    float4 t0 = f4maf(wB1, Up[2], f4maf(wB0, Up[0], make_float4(0,0,0,0)));
    float4 t1 = f4maf(wB1, Up[3], f4maf(wB0, Up[1], make_float4(0,0,0,0)));
    tt[0]=t0.x; tt[1]=t0.y; tt[2]=t0.z; tt[3]=t0.w;
    tt[4]=t1.x; tt[5]=t1.y; tt[6]=t1.z; tt[7]=t1.w;
  }

  const float* Ab = &sAB[((2 + p)*34)*68];
  const float* Bb = &sAB[(p*34)*68];
  const float* Mp = &s_M[p*512];
  const float4* fb4 = (const float4*)s_fb;

  #pragma unroll
  for (int i4 = 0; i4 < 4; i4++) {
    const int o4 = q*4 + i4;
    float4 A0 = *(const float4*)&Ab[lbA*68 + o4*4];
    float4 A1 = *(const float4*)&Ab[(lbA+1)*68 + o4*4];
    float4 B0 = *(const float4*)&Bb[lbB*68 + o4*4];
    float4 B1 = *(const float4*)&Bb[(lbB+1)*68 + o4*4];
    float4 r = fb4[o4];
    r = f4maf(wA0, A0, r); r = f4maf(wA1, A1, r);
    r = f4maf(wB0, B0, r); r = f4maf(wB1, B1, r);
    #pragma unroll
    for (int j = 0; j < 8; j++) {
      float4 m4 = *(const float4*)&Mp[j*64 + o4*4];
      r = f4maf(tt[j], m4, r);
    }
    float* op = out + ((size_t)(b*CC + o4*4)*HOUT + Y)*WOUT + X0 + u;
    op[0]              = r.x;
    op[HOUT*WOUT]      = r.y;
    op[2*HOUT*WOUT]    = r.z;
    op[3*HOUT*WOUT]    = r.w;
  }
}

// ---------------------------------------------------------------------------
extern "C" void kernel_launch(void* const* d_in, const int* in_sizes, int n_in,
                              void* d_out, int out_size) {
  const float* x    = (const float*)d_in[0];
  const float* st   = (const float*)d_in[1];
  const float* kcw  = (const float*)d_in[2];
  const float* kcb  = (const float*)d_in[3];
  const float* wc   = (const float*)d_in[4];
  const float* we   = (const float*)d_in[5];
  const float* b1w  = (const float*)d_in[6];
  const float* b1b  = (const float*)d_in[7];
  const float* b2w  = (const float*)d_in[8];
  const float* b2b  = (const float*)d_in[9];
  const float* rw   = (const float*)d_in[10];
  const float* rb   = (const float*)d_in[11];
  const float* ow   = (const float*)d_in[12];
  const float* ob   = (const float*)d_in[13];
  const float* sow  = (const float*)d_in[14];
  const float* sob  = (const float*)d_in[15];
  const float* fusw = (const float*)d_in[16];
  const float* fusb = (const float*)d_in[17];
  float* out = (float*)d_out;

  const int smem2 = K2_SMEM_FLOATS * 4;
  cudaFuncSetAttribute(k2_sta_mma, cudaFuncAttributeMaxDynamicSharedMemorySize, smem2);

  k01_prep<<<104, 256>>>(kcw, b1w, b1b, b2w, b2b, rw, rb, ow, ob, sow, sob, wc, we, fusw);
  k2_sta_mma<<<dim3(WIN/32, HIN/2, BB), 256, smem2>>>(x, st, kcb, fusw);
  k3_fuse<<<dim3(WOUT/64, HOUT, BB), 256>>>(fusb, out);
}

// round 17
// speedup vs baseline: 1.0613x; 1.0613x over previous
#include <cuda_runtime.h>
#include <cuda_bf16.h>
#include <cuda_fp16.h>
#include <cstdint>

#define BB 4
#define CC 64
#define HIN 96
#define WIN 96
#define HOUT 192
#define WOUT 192
#define NPX (HIN*WIN)          // 9216

// Scratch + precomputed data (allocation-free rule: device globals)
__device__ float g_A[BB*NPX*CC];         // fusL@sta, channel-last [b][px][64]
__device__ float g_B[BB*NPX*CC];         // fusR@x,   channel-last
__device__ float g_U[BB*4*NPX*8];        // wc_ci @ x, [b][ci][src][8]
__device__ float g_off[4][2];
__device__ float g_stoff[4][2];
__device__ float g_wcpx[4][512];         // [j*64+c]
__device__ float g_M[4][512];            // [j*64+o]  (fusR @ we_par)
// kc_w repacked: [t 25][q 8][ks 4][lane 32] uint2 = (b0h, b1h) fp16x2 (hi only)
__device__ uint2 g_b[25600];

// ============================ helpers ======================================
__device__ __forceinline__ uint32_t smem_u32(const void* p) {
  uint32_t a;
  asm("{ .reg .u64 t; cvta.to.shared.u64 t, %1; cvt.u32.u64 %0, t; }" : "=r"(a) : "l"(p));
  return a;
}
__device__ __forceinline__ void cp16(uint32_t dst, const float* src) {
  asm volatile("cp.async.cg.shared.global [%0], [%1], 16;" :: "r"(dst), "l"(src));
}
#define CP_COMMIT() asm volatile("cp.async.commit_group;" ::: "memory")
#define CP_WAIT0()  asm volatile("cp.async.wait_group 0;" ::: "memory")

__device__ __forceinline__ uint32_t fp16_pack2(float v0, float v1) {
  __half2 h = __floats2half2_rn(v0, v1);
  return *(uint32_t*)&h;
}

#define MMA_FP16(d, a, b0v, b1v) \
  asm volatile("mma.sync.aligned.m16n8k16.row.col.f32.f16.f16.f32 " \
      "{%0,%1,%2,%3}, {%4,%5,%6,%7}, {%8,%9}, {%0,%1,%2,%3};" \
      : "+f"((d)[0]), "+f"((d)[1]), "+f"((d)[2]), "+f"((d)[3]) \
      : "r"((a)[0]), "r"((a)[1]), "r"((a)[2]), "r"((a)[3]), "r"(b0v), "r"(b1v))

__device__ __forceinline__ float4 f4maf(float s, float4 a, float4 r) {
  r.x = fmaf(s, a.x, r.x); r.y = fmaf(s, a.y, r.y);
  r.z = fmaf(s, a.z, r.z); r.w = fmaf(s, a.w, r.w);
  return r;
}

// ---------------------------------------------------------------------------
// K0: ONE kernel, three independent block classes (latency hiding):
//   blocks 0..287   : B = fusR @ x (channel-last), 128px tiles
//   blocks 288..387 : repack kc_w -> fp16 fragments
//   blocks 388..391 : per-parity MLP -> offsets, wc_px, M
// ---------------------------------------------------------------------------
#define K0_SMEM_FLOATS (8256 + 4352)

__global__ __launch_bounds__(256) void k0_prep(const float* __restrict__ x,
                         const float* __restrict__ kcw,
                         const float* __restrict__ b1w, const float* __restrict__ b1b,
                         const float* __restrict__ b2w, const float* __restrict__ b2b,
                         const float* __restrict__ rw,  const float* __restrict__ rb,
                         const float* __restrict__ ow,  const float* __restrict__ ob,
                         const float* __restrict__ sow, const float* __restrict__ sob,
                         const float* __restrict__ wc,  const float* __restrict__ we,
                         const float* __restrict__ fusw) {
  extern __shared__ float sm[];
  const int bid = blockIdx.x, tid = threadIdx.x;

  if (bid < 288) {
    // ---------------- B GEMM: 64o x 128px, K=64 ----------------
    float* s_src = sm;           // [c 64][px 129]
    float* s_wT  = sm + 8256;    // [k 64][o 68]  (fusR^T)
    const int px0 = (bid % 72)*128, b = bid / 72;
    const float* xb = x + (size_t)b*CC*NPX;

    for (int e = tid; e < 8192; e += 256) {
      int k = e >> 7, p = e & 127;
      s_src[k*129 + p] = xb[(size_t)k*NPX + px0 + p];
    }
    for (int e = tid; e < 4096; e += 256) {
      int o = e >> 6, k = e & 63;
      s_wT[k*68 + o] = fusw[o*128 + 64 + k];
    }
    __syncthreads();

    const int o0 = (tid & 15)*4, p0 = (tid >> 4)*8;
    float4 acc[8];
    #pragma unroll
    for (int i = 0; i < 8; i++) acc[i] = make_float4(0.f, 0.f, 0.f, 0.f);
    #pragma unroll 4
    for (int k = 0; k < 64; k++) {
      float4 w4 = *(const float4*)&s_wT[k*68 + o0];
      const float* sr = s_src + k*129 + p0;
      #pragma unroll
      for (int pp = 0; pp < 8; pp++)
        acc[pp] = f4maf(sr[pp], w4, acc[pp]);
    }
    float* dst = g_B + (size_t)b*NPX*CC;
    #pragma unroll
    for (int pp = 0; pp < 8; pp++)
      *(float4*)&dst[(size_t)(px0 + p0 + pp)*CC + o0] = acc[pp];
    return;
  }

  if (bid < 388) {
    // ---------------- repack kc_w -> fp16 fragments ----------------
    int idx = (bid - 288)*256 + tid;
    int l  = idx & 31;
    int ks = (idx >> 5) & 3;
    int q  = (idx >> 7) & 7;
    int t  = idx >> 10;
    int g = l >> 2, tg = l & 3;
    int c  = q*8 + g;
    int k0 = ks*16 + 2*tg;
    const float* row = kcw + (c*25 + t)*64;
    g_b[idx] = make_uint2(fp16_pack2(row[k0],     row[k0 + 1]),
                          fp16_pack2(row[k0 + 8], row[k0 + 9]));
    return;
  }

  // ---------------- parity MLP (4 blocks) ----------------
  float* hid   = sm;            // 64
  float* emb   = sm + 64;       // 64
  float* r     = sm + 128;      // 4
  float* s_we2 = sm + 136;      // 512
  float* s_fr  = sm + 648;      // 64*65 = 4160
  const int ci = bid - 388;
  const float in2 = (ci >> 1) ? 0.25f : -0.25f;
  const float in3 = (ci & 1)  ? 0.25f : -0.25f;

  for (int e = tid; e < 4096; e += 256) {
    int o = e >> 6, c = e & 63;
    s_fr[c*65 + o] = fusw[o*128 + 64 + c];
  }
  if (tid < 64) {
    float a = b1b[tid] + 0.5f*b1w[tid*4+0] + 0.5f*b1w[tid*4+1]
            + in2*b1w[tid*4+2] + in3*b1w[tid*4+3];
    hid[tid] = fmaxf(a, 0.f);
  }
  __syncthreads();
  if (tid < 64) {
    float a = b2b[tid];
    #pragma unroll 8
    for (int k = 0; k < 64; k++) a = fmaf(b2w[tid*64+k], hid[k], a);
    emb[tid] = fmaxf(a, 0.f);
  }
  __syncthreads();
  if (tid < 4) {
    float a = rb[tid];
    #pragma unroll 8
    for (int k = 0; k < 64; k++) a = fmaf(rw[tid*64+k], emb[k], a);
    r[tid] = 1.f / (1.f + expf(-a));
  } else if (tid < 6) {
    int t = tid - 4; float a = ob[t];
    #pragma unroll 8
    for (int k = 0; k < 64; k++) a = fmaf(ow[t*64+k], emb[k], a);
    g_off[ci][t] = a;
  } else if (tid < 8) {
    int t = tid - 6; float a = sob[t];
    #pragma unroll 8
    for (int k = 0; k < 64; k++) a = fmaf(sow[t*64+k], emb[k], a);
    g_stoff[ci][t] = a;
  }
  __syncthreads();
  for (int e = tid; e < 512; e += 256) {
    float a = 0.f, bsum = 0.f;
    #pragma unroll
    for (int ex = 0; ex < 4; ex++) {
      a    = fmaf(r[ex], wc[ex*512+e], a);
      bsum = fmaf(r[ex], we[ex*512+e], bsum);
    }
    g_wcpx[ci][e] = a;
    s_we2[e] = bsum;
  }
  __syncthreads();
  for (int e = tid; e < 512; e += 256) {
    int j = e >> 6, o = e & 63;
    float a = 0.f;
    #pragma unroll 8
    for (int c = 0; c < 64; c++) a = fmaf(s_fr[c*65 + o], s_we2[c*8 + j], a);
    g_M[ci][j*64 + o] = a;
  }
}

// ---------------------------------------------------------------------------
// K2 v12: fp16 single-term mma loop + fused epilogue computing
// A = fusL@sta and U = wc_ci@x  (B moved to k0).
// Block: 256 thr / 8 warps, tile (b, 2 rows, 32 px), M=64. 3 blocks/SM.
// ---------------------------------------------------------------------------
#define K2_SMEM_FLOATS (4096 + 6912 + 1600)

__global__ __launch_bounds__(256, 3) void k2_sta_mma(const float* __restrict__ x,
                                                     const float* __restrict__ st,
                                                     const float* __restrict__ kcb,
                                                     const float* __restrict__ fusw) {
  extern __shared__ float sm[];
  float* s_b  = sm;                // [2][512 uint4] = 2x8KB
  float* s_x  = sm + 4096;         // [c 64][slot 3][36]
  float* s_kb = sm + 11008;        // [1600]
  // post-loop reuse:
  float* s_sta = sm;               // phase A: sta tile; phase U: x tile
  float* s_fl  = sm + 4224;        // fusL^T [k][68]
  float* s_wc  = sm + 8576;        // [4][512]

  const int b = blockIdx.z, h0 = blockIdx.y*2, w0 = blockIdx.x*32;
  const int tid = threadIdx.x, wid = tid >> 5, l = tid & 31;
  const int g = l >> 2, tg = l & 3;
  const int mt = wid & 3, nth = wid >> 2;
  const uint32_t sb = smem_u32(s_b);

  // B(0) prologue: 8KB = 512 x 16B chunks
  {
    const float* src = (const float*)g_b;
    #pragma unroll
    for (int i = 0; i < 2; i++) {
      int j = tid + i*256;
      cp16(sb + (uint32_t)j*16u, src + j*4);
    }
    CP_COMMIT();
  }

  // x rows 0..2 into slots 0..2
  for (int e = tid; e < 64*3*36; e += 256) {
    int col = e % 36; int slot = (e / 36) % 3; int c = e / 108;
    int gy = min(max(h0 - 2 + slot, 0), HIN - 1);
    int gx = min(max(w0 - 2 + col, 0), WIN - 1);
    s_x[c*108 + slot*36 + col] = x[((b*CC + c)*HIN + gy)*WIN + gx];
  }
  for (int e = tid; e < 1600; e += 256) s_kb[e] = kcb[e];

  // A fragments (fp16 hi) direct from gmem, tap-invariant
  uint32_t ahi[4][4];
  {
    const int pxg = mt*16 + g, pxg8 = pxg + 8;
    const int r0 = h0 + (pxg >> 5),  ca = w0 + (pxg & 31);
    const int r1 = h0 + (pxg8 >> 5), cb2 = w0 + (pxg8 & 31);
    const float* stb = st + (size_t)b*CC*NPX;
    #pragma unroll
    for (int ks = 0; ks < 4; ks++) {
      int kb = ks*16 + 2*tg;
      const float* p0 = stb + (size_t)kb*NPX;
      ahi[ks][0] = fp16_pack2(p0[r0*WIN + ca],         p0[NPX + r0*WIN + ca]);
      ahi[ks][1] = fp16_pack2(p0[r1*WIN + cb2],        p0[NPX + r1*WIN + cb2]);
      ahi[ks][2] = fp16_pack2(p0[8*NPX + r0*WIN + ca], p0[9*NPX + r0*WIN + ca]);
      ahi[ks][3] = fp16_pack2(p0[8*NPX + r1*WIN + cb2], p0[9*NPX + r1*WIN + cb2]);
    }
  }
  __syncthreads();

  float sacc[16];
  #pragma unroll
  for (int i = 0; i < 16; i++) sacc[i] = 0.f;

  const int prow  = mt >> 1;
  const int pcol0 = (mt & 1)*16 + g;

  for (int t = 0; t < 25; t++) {
    const int buf = t & 1;
    CP_WAIT0();
    __syncthreads();
    if (t < 24) {
      const float* src = (const float*)(g_b + (t + 1)*1024);
      const uint32_t nb = sb + (uint32_t)(1 - buf)*8192u;
      #pragma unroll
      for (int i = 0; i < 2; i++) {
        int j = tid + i*256;
        cp16(nb + (uint32_t)j*16u, src + j*4);
      }
      CP_COMMIT();
    }
    if (t == 5 || t == 10 || t == 15) {
      const int rl = t/5 + 2;
      const int slot = rl % 3;
      const int gy = min(max(h0 - 2 + rl, 0), HIN - 1);
      for (int e = tid; e < 2304; e += 256) {
        int col = e % 36; int c = e / 36;
        int gx = min(max(w0 - 2 + col, 0), WIN - 1);
        s_x[c*108 + slot*36 + col] = x[((b*CC + c)*HIN + gy)*WIN + gx];
      }
    }

    const int rr = t / 5, dw = t - rr*5;

    float d[4][4];
    #pragma unroll
    for (int n = 0; n < 4; n++) {
      int c0 = ((nth*4 + n)*8 + 2*tg)*25 + t;
      d[n][0] = s_kb[c0];      d[n][1] = s_kb[c0 + 25];
      d[n][2] = d[n][0];       d[n][3] = d[n][1];
    }

    const uint2* bb = (const uint2*)(s_b + buf*2048);
    #pragma unroll
    for (int ks = 0; ks < 4; ks++) {
      #pragma unroll
      for (int n = 0; n < 4; n++) {
        uint2 bv = bb[((nth*4 + n)*4 + ks)*32 + l];
        MMA_FP16(d[n], ahi[ks], bv.x, bv.y);   // ahi * bhi (single term)
      }
    }

    const int sl = (prow + rr) % 3;
    #pragma unroll
    for (int n = 0; n < 4; n++) {
      int cb = (nth*4 + n)*8 + 2*tg;
      #pragma unroll
      for (int j = 0; j < 4; j++) {
        int c  = cb + (j & 1);
        int px = pcol0 + (j >> 1)*8;
        float gv = d[n][j];
        float lv = fmaf(0.45f, fabsf(gv), 0.55f*gv);
        float xv = s_x[c*108 + sl*36 + px + dw];
        sacc[n*4 + j] = fmaf(lv, xv, sacc[n*4 + j]);
      }
    }
  }

  // ============ fused epilogue: A = fusL@sta, U = wc_ci@x =============
  const int o0 = (tid & 15)*4, p0 = (tid >> 4)*4;

  __syncthreads();   // all loop reads of s_b/s_x retired
  // phase A staging: spill sta tile + fusL^T + swc
  #pragma unroll
  for (int n = 0; n < 4; n++) {
    int cb = (nth*4 + n)*8 + 2*tg;
    #pragma unroll
    for (int j = 0; j < 4; j++) {
      int c  = cb + (j & 1);
      int px = prow*32 + pcol0 + (j >> 1)*8;
      s_sta[c*66 + px] = sacc[n*4 + j];
    }
  }
  for (int e = tid; e < 4096; e += 256) {
    int o = e >> 6, k = e & 63;
    s_fl[k*68 + o] = fusw[o*128 + k];
  }
  for (int e = tid; e < 2048; e += 256) s_wc[e] = g_wcpx[e >> 9][e & 511];
  __syncthreads();

  // A GEMM: 64o x 64px, K=64
  {
    float4 acc[4];
    #pragma unroll
    for (int i = 0; i < 4; i++) acc[i] = make_float4(0.f, 0.f, 0.f, 0.f);
    #pragma unroll 4
    for (int c = 0; c < 64; c++) {
      float4 w4 = *(const float4*)&s_fl[c*68 + o0];
      const float* sr = s_sta + c*66 + p0;
      #pragma unroll
      for (int pp = 0; pp < 4; pp++)
        acc[pp] = f4maf(sr[pp], w4, acc[pp]);
    }
    float* dst = g_A + (size_t)b*NPX*CC;
    #pragma unroll
    for (int pp = 0; pp < 4; pp++) {
      int pxt = p0 + pp;
      int gpx = (h0 + (pxt >> 5))*WIN + w0 + (pxt & 31);
      *(float4*)&dst[(size_t)gpx*CC + o0] = acc[pp];
    }
  }
  __syncthreads();   // A GEMM reads done before s_sta overwrite

  // phase U staging: x center tile [c][px 0..63]
  for (int e = tid; e < 4096; e += 256) {
    int c = e >> 6, px = e & 63;
    s_sta[c*66 + px] = x[((b*CC + c)*HIN + h0 + (px >> 5))*WIN + w0 + (px & 31)];
  }
  __syncthreads();

  // U: thread = (px 64, ci 4): 8 j-dots over c
  {
    const int px = tid & 63, ci = tid >> 6;
    float acc[8];
    #pragma unroll
    for (int j = 0; j < 8; j++) acc[j] = 0.f;
    #pragma unroll 4
    for (int c = 0; c < 64; c++) {
      float xv = s_sta[c*66 + px];
      const float* w = &s_wc[ci*512 + c];
      #pragma unroll
      for (int j = 0; j < 8; j++)
        acc[j] = fmaf(w[j*64], xv, acc[j]);
    }
    int gpx = (h0 + (px >> 5))*WIN + w0 + (px & 31);
    float* dst = g_U + ((size_t)(b*4 + ci)*NPX + gpx)*8;
    *(float4*)dst       = make_float4(acc[0], acc[1], acc[2], acc[3]);
    *(float4*)(dst + 4) = make_float4(acc[4], acc[5], acc[6], acc[7]);
  }
}

// ---------------------------------------------------------------------------
// K3 v4: staged + row-precombined bilinear taps; t via interp of U.
// ---------------------------------------------------------------------------
__global__ __launch_bounds__(256, 4) void k3_fuse(const float* __restrict__ fusb,
                                                  float* __restrict__ out) {
  __shared__ float sAB[4*34*68];
  __shared__ float sU[2*34*8];
  __shared__ float s_M[1024];
  __shared__ float s_fb[64];
  __shared__ float s_w0[2][64], s_w1[2][64];
  __shared__ int   s_lb[2][64];
  __shared__ int   s_rows[2][2][2];
  __shared__ float s_wy[2][2][2];
  __shared__ int   s_fc[2][2];
  __shared__ float s_frc[2][2];
  __shared__ int   s_base[2];

  const int b = blockIdx.z, Y = blockIdx.y, X0 = blockIdx.x * 64;
  const int tid = threadIdx.x;
  const int ph = Y & 1;

  if (tid < 2) {
    const int k = tid;
    int fc0 = 0, fc1 = 0;
    #pragma unroll
    for (int p = 0; p < 2; p++) {
      int ci = ph*2 + p;
      float offx = k ? g_stoff[ci][0] : g_off[ci][0];
      float offy = k ? g_stoff[ci][1] : g_off[ci][1];
      float pyf = (Y + 0.5f)*0.5f - 0.5f + offy;
      float yf = floorf(pyf); int iy = (int)yf; float fy = pyf - yf;
      s_wy[k][p][0] = (iy   >= 0 && iy   <= HIN-1) ? (1.f - fy) : 0.f;
      s_wy[k][p][1] = (iy+1 >= 0 && iy+1 <= HIN-1) ? fy : 0.f;
      s_rows[k][p][0] = min(max(iy, 0), HIN-1);
      s_rows[k][p][1] = min(max(iy+1, 0), HIN-1);
      float xo = (p ? 0.25f : -0.25f) + offx;
      float xf = floorf(xo); int fc = (int)xf;
      s_fc[k][p] = fc; s_frc[k][p] = xo - xf;
      if (p == 0) fc0 = fc; else fc1 = fc;
    }
    s_base[k] = X0/2 + min(fc0, fc1);
  }
  __syncthreads();

  if (tid < 128) {
    int k = tid >> 6, u = tid & 63, p = u & 1;
    int sg = X0/2 + (u >> 1) + s_fc[k][p];
    float fr = s_frc[k][p];
    s_lb[k][u] = sg - s_base[k];
    s_w0[k][u] = (sg   >= 0 && sg   <= WIN-1) ? (1.f - fr) : 0.f;
    s_w1[k][u] = (sg+1 >= 0 && sg+1 <= WIN-1) ? fr : 0.f;
  }

  for (int e = tid; e < 2176; e += 256) {
    int kp = e / 544, rem = e - kp*544;
    int i = rem >> 4, c4 = rem & 15;
    int k = kp >> 1, p = kp & 1;
    int cg = min(max(s_base[k] + i, 0), WIN-1);
    const float4* src = (const float4*)(k ? g_A : g_B) + (size_t)(b*NPX)*16;
    float4 v0 = src[(s_rows[k][p][0]*WIN + cg)*16 + c4];
    float4 v1 = src[(s_rows[k][p][1]*WIN + cg)*16 + c4];
    float wy0 = s_wy[k][p][0], wy1 = s_wy[k][p][1];
    float4 vv;
    vv.x = wy0*v0.x + wy1*v1.x;  vv.y = wy0*v0.y + wy1*v1.y;
    vv.z = wy0*v0.z + wy1*v1.z;  vv.w = wy0*v0.w + wy1*v1.w;
    *(float4*)&sAB[(kp*34 + i)*68 + c4*4] = vv;
  }
  if (tid < 136) {
    int p = tid / 68, rem = tid - p*68;
    int i = rem >> 1, h = rem & 1;
    int ci = ph*2 + p;
    int cg = min(max(s_base[0] + i, 0), WIN-1);
    const float4* src = (const float4*)g_U + ((size_t)(b*4 + ci)*NPX)*2;
    float4 u0 = src[(s_rows[0][p][0]*WIN + cg)*2 + h];
    float4 u1 = src[(s_rows[0][p][1]*WIN + cg)*2 + h];
    float wy0 = s_wy[0][p][0], wy1 = s_wy[0][p][1];
    float4 vv;
    vv.x = wy0*u0.x + wy1*u1.x;  vv.y = wy0*u0.y + wy1*u1.y;
    vv.z = wy0*u0.z + wy1*u1.z;  vv.w = wy0*u0.w + wy1*u1.w;
    *(float4*)&sU[(p*34 + i)*8 + h*4] = vv;
  }
  for (int e = tid; e < 1024; e += 256)
    s_M[e] = g_M[ph*2 + (e >> 9)][e & 511];
  if (tid < 64) s_fb[tid] = fusb[tid];
  __syncthreads();

  const int u = tid & 63, q = tid >> 6, p = u & 1;
  const int   lbB = s_lb[0][u], lbA = s_lb[1][u];
  const float wB0 = s_w0[0][u], wB1 = s_w1[0][u];
  const float wA0 = s_w0[1][u], wA1 = s_w1[1][u];

  float tt[8];
  {
    const float4* Up = (const float4*)&sU[(p*34 + lbB)*8];
    float4 t0 = f4maf(wB1, Up[2], f4maf(wB0, Up[0], make_float4(0,0,0,0)));
    float4 t1 = f4maf(wB1, Up[3], f4maf(wB0, Up[1], make_float4(0,0,0,0)));
    tt[0]=t0.x; tt[1]=t0.y; tt[2]=t0.z; tt[3]=t0.w;
    tt[4]=t1.x; tt[5]=t1.y; tt[6]=t1.z; tt[7]=t1.w;
  }

  const float* Ab = &sAB[((2 + p)*34)*68];
  const float* Bb = &sAB[(p*34)*68];
  const float* Mp = &s_M[p*512];
  const float4* fb4 = (const float4*)s_fb;

  #pragma unroll
  for (int i4 = 0; i4 < 4; i4++) {
    const int o4 = q*4 + i4;
    float4 A0 = *(const float4*)&Ab[lbA*68 + o4*4];
    float4 A1 = *(const float4*)&Ab[(lbA+1)*68 + o4*4];
    float4 B0 = *(const float4*)&Bb[lbB*68 + o4*4];
    float4 B1 = *(const float4*)&Bb[(lbB+1)*68 + o4*4];
    float4 r = fb4[o4];
    r = f4maf(wA0, A0, r); r = f4maf(wA1, A1, r);
    r = f4maf(wB0, B0, r); r = f4maf(wB1, B1, r);
    #pragma unroll
    for (int j = 0; j < 8; j++) {
      float4 m4 = *(const float4*)&Mp[j*64 + o4*4];
      r = f4maf(tt[j], m4, r);
    }
    float* op = out + ((size_t)(b*CC + o4*4)*HOUT + Y)*WOUT + X0 + u;
    op[0]              = r.x;
    op[HOUT*WOUT]      = r.y;
    op[2*HOUT*WOUT]    = r.z;
    op[3*HOUT*WOUT]    = r.w;
  }
}

// ---------------------------------------------------------------------------
extern "C" void kernel_launch(void* const* d_in, const int* in_sizes, int n_in,
                              void* d_out, int out_size) {
  const float* x    = (const float*)d_in[0];
  const float* st   = (const float*)d_in[1];
  const float* kcw  = (const float*)d_in[2];
  const float* kcb  = (const float*)d_in[3];
  const float* wc   = (const float*)d_in[4];
  const float* we   = (const float*)d_in[5];
  const float* b1w  = (const float*)d_in[6];
  const float* b1b  = (const float*)d_in[7];
  const float* b2w  = (const float*)d_in[8];
  const float* b2b  = (const float*)d_in[9];
  const float* rw   = (const float*)d_in[10];
  const float* rb   = (const float*)d_in[11];
  const float* ow   = (const float*)d_in[12];
  const float* ob   = (const float*)d_in[13];
  const float* sow  = (const float*)d_in[14];
  const float* sob  = (const float*)d_in[15];
  const float* fusw = (const float*)d_in[16];
  const float* fusb = (const float*)d_in[17];
  float* out = (float*)d_out;

  const int smem0 = K0_SMEM_FLOATS * 4;
  const int smem2 = K2_SMEM_FLOATS * 4;
  cudaFuncSetAttribute(k0_prep,    cudaFuncAttributeMaxDynamicSharedMemorySize, smem0);
  cudaFuncSetAttribute(k2_sta_mma, cudaFuncAttributeMaxDynamicSharedMemorySize, smem2);

  k0_prep<<<392, 256, smem0>>>(x, kcw, b1w, b1b, b2w, b2b, rw, rb, ow, ob,
                               sow, sob, wc, we, fusw);
  k2_sta_mma<<<dim3(WIN/32, HIN/2, BB), 256, smem2>>>(x, st, kcb, fusw);
  k3_fuse<<<dim3(WOUT/64, HOUT, BB), 256>>>(fusb, out);
}